// round 5
// baseline (speedup 1.0000x reference)
#include <cuda_runtime.h>
#include <cuda_bf16.h>

// ---------------------------------------------------------------------------
// ZBL screened-Coulomb pair energy with switching polynomial, scatter to atoms
//
// Inputs (metadata order):
//   0: rij            float32 [E]
//   1: covalent_radii float32 [4]
//   2: atomic_numbers float32 [4]
//   3: first_atom     int32   [E]
//   4: second_atom    int32   [E]
//   5: atom_type_index int32  [N]
//   (6: n_atoms scalar, unused; we use out_size)
// Output: float32 [N]
// ---------------------------------------------------------------------------

#define MAX_PACK_WORDS 16384   // supports up to 262144 atoms at 2 bits/atom

__device__ float        g_table[16 * 12];
__device__ unsigned int g_packed[MAX_PACK_WORDS];

// ---- zero the output ------------------------------------------------------
__global__ void zbl_zero(float* __restrict__ out, int n) {
    int i = blockIdx.x * blockDim.x + threadIdx.x;
    if (i < n) out[i] = 0.0f;
}

// ---- build 16-entry pair table (fp64, one warp, once per launch) ----------
__global__ void zbl_prep_table(const float* __restrict__ cr,
                               const float* __restrict__ Z) {
    int p = threadIdx.x;
    if (p >= 16) return;
    int ti = p >> 2, tj = p & 3;

    const double c[4] = {0.02817, 0.28022, 0.50986, 0.18175};
    const double d[4] = {0.20162, 0.4029, 0.94229, 3.1998};
    const double COULOMB = 14.399645478425668;
    const double A0 = 0.4685, P = 0.23;

    double zi = (double)Z[ti], zj = (double)Z[tj];
    double a  = A0 / (pow(zi, P) + pow(zj, P));
    double rc = (double)cr[ti] + (double)cr[tj];

    double da[4], phi = 0.0, dphi = 0.0, d2phi = 0.0;
#pragma unroll
    for (int k = 0; k < 4; k++) {
        da[k] = d[k] / a;
        double ex = exp(-rc * da[k]);
        phi   += c[k] * ex;
        dphi  += -c[k] * da[k] * ex;
        d2phi += c[k] * da[k] * da[k] * ex;
    }
    double factor = COULOMB * zi * zj;
    double ec   = factor / rc * phi;
    double dec  = factor / rc * (-phi / rc + dphi);
    double d2ec = factor / rc * (d2phi - 2.0 / rc * dphi + 2.0 * phi / (rc * rc));

    double A = (-3.0 * dec + rc * d2ec) / (rc * rc);
    double B = ( 2.0 * dec - rc * d2ec) / (rc * rc * rc);
    double C = -ec + rc * dec / 2.0 - rc * rc * d2ec / 12.0;

    float* t = &g_table[p * 12];
    t[0] = (float)da[0];
    t[1] = (float)da[1];
    t[2] = (float)da[2];
    t[3] = (float)da[3];
    t[4] = (float)(0.5 * factor);   // halfFactor (folds e/2)
    t[5] = (float)rc;
    t[6] = (float)(A / 6.0);        // A/3 * 1/2
    t[7] = (float)(B / 8.0);        // B/4 * 1/2
    t[8] = (float)(C / 2.0);
    t[9] = 0.0f; t[10] = 0.0f; t[11] = 0.0f;
}

// ---- pack atom types to 2 bits/atom (16 atoms per uint32) -----------------
__global__ void zbl_pack_types(const int* __restrict__ type, int n_atoms) {
    int w  = blockIdx.x * blockDim.x + threadIdx.x;
    int nw = (n_atoms + 15) >> 4;
    if (w >= nw) return;
    unsigned v = 0;
    int base = w << 4;
    int lim  = n_atoms - base;
    if (lim > 16) lim = 16;
    for (int k = 0; k < lim; k++)
        v |= ((unsigned)type[base + k] & 3u) << (2 * k);
    g_packed[w] = v;
}

// ---- per-edge kernel ------------------------------------------------------
__device__ __forceinline__ void zbl_edge(float r, int i, int j,
                                         const float* __restrict__ tab,
                                         const unsigned* __restrict__ pk,
                                         float* __restrict__ out) {
    unsigned wi = pk[i >> 4];
    unsigned wj = pk[j >> 4];
    int ti = (wi >> ((i & 15) * 2)) & 3;
    int tj = (wj >> ((j & 15) * 2)) & 3;
    const float* t = tab + ((ti << 2) + tj) * 12;
    float4 t0 = *(const float4*)(t);       // da0..da3
    float4 t1 = *(const float4*)(t + 4);   // halfFactor, rc, A/6, B/8
    float  C2 = t[8];
    if (r <= t1.y) {
        float s = 0.02817f * __expf(-r * t0.x)
                + 0.28022f * __expf(-r * t0.y)
                + 0.50986f * __expf(-r * t0.z)
                + 0.18175f * __expf(-r * t0.w);
        float r2  = r * r;
        float val = t1.x * __fdividef(s, r) + r2 * r * (t1.z + t1.w * r) + C2;
        atomicAdd(out + i, val);
    }
}

__global__ __launch_bounds__(256)
void zbl_edge_kernel(const float* __restrict__ rij,
                     const int*   __restrict__ fa,
                     const int*   __restrict__ sa,
                     float*       __restrict__ out,
                     int E, int n_atoms) {
    extern __shared__ unsigned sh[];
    float*    sh_tab  = (float*)sh;        // 192 floats
    unsigned* sh_pack = sh + 192;          // nw words

    int nw = (n_atoms + 15) >> 4;
    for (int k = threadIdx.x; k < 192; k += blockDim.x)
        sh_tab[k] = g_table[k];
    for (int k = threadIdx.x; k < nw; k += blockDim.x)
        sh_pack[k] = g_packed[k];
    __syncthreads();

    int nvec = E >> 2;
    const float4* r4p = (const float4*)rij;
    const int4*   f4p = (const int4*)fa;
    const int4*   s4p = (const int4*)sa;

    for (int v = blockIdx.x * blockDim.x + threadIdx.x; v < nvec;
         v += gridDim.x * blockDim.x) {
        float4 r4 = r4p[v];
        int4   f4 = f4p[v];
        int4   s4 = s4p[v];
        zbl_edge(r4.x, f4.x, s4.x, sh_tab, sh_pack, out);
        zbl_edge(r4.y, f4.y, s4.y, sh_tab, sh_pack, out);
        zbl_edge(r4.z, f4.z, s4.z, sh_tab, sh_pack, out);
        zbl_edge(r4.w, f4.w, s4.w, sh_tab, sh_pack, out);
    }

    // tail (E not divisible by 4)
    int tail = E & 3;
    if (blockIdx.x == 0 && (int)threadIdx.x < tail) {
        int e = (nvec << 2) + threadIdx.x;
        zbl_edge(rij[e], fa[e], sa[e], sh_tab, sh_pack, out);
    }
}

// ---------------------------------------------------------------------------
extern "C" void kernel_launch(void* const* d_in, const int* in_sizes, int n_in,
                              void* d_out, int out_size) {
    const float* rij = (const float*)d_in[0];
    const float* cr  = (const float*)d_in[1];
    const float* Z   = (const float*)d_in[2];
    const int*   fa  = (const int*)d_in[3];
    const int*   sa  = (const int*)d_in[4];
    const int*   ty  = (const int*)d_in[5];
    int E       = in_sizes[0];
    int n_atoms = out_size;

    float* out = (float*)d_out;

    zbl_zero<<<(n_atoms + 255) / 256, 256>>>(out, n_atoms);
    zbl_prep_table<<<1, 16>>>(cr, Z);
    int nw = (n_atoms + 15) >> 4;
    zbl_pack_types<<<(nw + 255) / 256, 256>>>(ty, n_atoms);

    size_t shbytes = 192 * sizeof(float) + (size_t)nw * sizeof(unsigned);
    cudaFuncSetAttribute(zbl_edge_kernel,
                         cudaFuncAttributeMaxDynamicSharedMemorySize,
                         (int)((shbytes + 1023) & ~1023ull));
    zbl_edge_kernel<<<608, 256, shbytes>>>(rij, fa, sa, out, E, n_atoms);
}

// round 6
// speedup vs baseline: 1.3827x; 1.3827x over previous
#include <cuda_runtime.h>
#include <cuda_bf16.h>

// ---------------------------------------------------------------------------
// ZBL screened-Coulomb pair energy with switching polynomial, scatter to atoms
//
// Inputs (metadata order):
//   0: rij             float32 [E]
//   1: covalent_radii  float32 [4]
//   2: atomic_numbers  float32 [4]
//   3: first_atom      int32   [E]
//   4: second_atom     int32   [E]
//   5: atom_type_index int32   [N]
// Output: float32 [N]
// ---------------------------------------------------------------------------

#define MAX_PACK_WORDS 16384   // up to 262144 atoms at 2 bits/atom

__device__ unsigned int g_packed[MAX_PACK_WORDS];

// ---- fused: zero output + pack atom types to 2 bits/atom ------------------
__global__ void zbl_setup(const int* __restrict__ type,
                          float* __restrict__ out, int n_atoms) {
    int i = blockIdx.x * blockDim.x + threadIdx.x;
    if (i < n_atoms) out[i] = 0.0f;
    int nw = (n_atoms + 15) >> 4;
    if (i < nw) {
        unsigned v = 0;
        int base = i << 4;
        int lim  = n_atoms - base;
        if (lim > 16) lim = 16;
        for (int k = 0; k < lim; k++)
            v |= ((unsigned)type[base + k] & 3u) << (2 * k);
        g_packed[i] = v;
    }
}

// ---- per-edge math --------------------------------------------------------
// tabA[p] = (rc, inv_a, halfFactor, A/6)   tabB[p] = (B/8, C/2)
__device__ __forceinline__ void zbl_edge(float r, int i, int j,
                                         const float4* __restrict__ tabA,
                                         const float2* __restrict__ tabB,
                                         float* __restrict__ out) {
    unsigned wi = __ldg(&g_packed[i >> 4]);
    unsigned wj = __ldg(&g_packed[j >> 4]);
    int ti = (wi >> ((i & 15) * 2)) & 3;
    int tj = (wj >> ((j & 15) * 2)) & 3;
    int p  = (ti << 2) | tj;
    float4 a4 = tabA[p];
    if (r <= a4.x) {
        float2 b2 = tabB[p];
        float x = -r * a4.y;          // -r / a
        // d_k * log2(e), so exp2f maps straight to MUFU.EX2
        float s = 0.02817f * exp2f(0.29088274f * x)
                + 0.28022f * exp2f(0.58126184f * x)
                + 0.50986f * exp2f(1.35944400f * x)
                + 0.18175f * exp2f(4.61651600f * x);
        float r3  = r * r * r;
        float val = a4.z * __fdividef(s, r) + r3 * (a4.w + b2.x * r) + b2.y;
        atomicAdd(out + i, val);
    }
}

__global__ __launch_bounds__(256, 8)
void zbl_edge_kernel(const float* __restrict__ rij,
                     const int*   __restrict__ fa,
                     const int*   __restrict__ sa,
                     const float* __restrict__ cr,
                     const float* __restrict__ Z,
                     float*       __restrict__ out,
                     int E) {
    __shared__ float4 tabA[16];
    __shared__ float2 tabB[16];

    if (threadIdx.x < 16) {
        int p = threadIdx.x;
        int ti = p >> 2, tj = p & 3;
        const float c[4] = {0.02817f, 0.28022f, 0.50986f, 0.18175f};
        const float d[4] = {0.20162f, 0.4029f, 0.94229f, 3.1998f};
        float zi = Z[ti], zj = Z[tj];
        float a     = 0.4685f / (powf(zi, 0.23f) + powf(zj, 0.23f));
        float inv_a = 1.0f / a;
        float rc    = cr[ti] + cr[tj];
        float phi = 0.f, dphi = 0.f, d2phi = 0.f;
#pragma unroll
        for (int k = 0; k < 4; k++) {
            float da = d[k] * inv_a;
            float ex = expf(-rc * da);
            phi   += c[k] * ex;
            dphi  -= c[k] * da * ex;
            d2phi += c[k] * da * da * ex;
        }
        float factor = 14.399645478425668f * zi * zj;
        float irc  = 1.0f / rc;
        float ec   = factor * irc * phi;
        float dec  = factor * irc * (-phi * irc + dphi);
        float d2ec = factor * irc * (d2phi - 2.0f * irc * dphi
                                     + 2.0f * phi * irc * irc);
        float A = (-3.0f * dec + rc * d2ec) * irc * irc;
        float B = ( 2.0f * dec - rc * d2ec) * irc * irc * irc;
        float C = -ec + rc * dec * 0.5f - rc * rc * d2ec * (1.0f / 12.0f);
        tabA[p] = make_float4(rc, inv_a, 0.5f * factor, A * (1.0f / 6.0f));
        tabB[p] = make_float2(B * 0.125f, C * 0.5f);
    }
    __syncthreads();

    int nvec = E >> 2;
    const float4* r4p = (const float4*)rij;
    const int4*   f4p = (const int4*)fa;
    const int4*   s4p = (const int4*)sa;

    for (int v = blockIdx.x * blockDim.x + threadIdx.x; v < nvec;
         v += gridDim.x * blockDim.x) {
        float4 r4 = r4p[v];
        int4   f4 = f4p[v];
        int4   s4 = s4p[v];
        zbl_edge(r4.x, f4.x, s4.x, tabA, tabB, out);
        zbl_edge(r4.y, f4.y, s4.y, tabA, tabB, out);
        zbl_edge(r4.z, f4.z, s4.z, tabA, tabB, out);
        zbl_edge(r4.w, f4.w, s4.w, tabA, tabB, out);
    }

    int tail = E & 3;
    if (blockIdx.x == 0 && (int)threadIdx.x < tail) {
        int e = (nvec << 2) + threadIdx.x;
        zbl_edge(rij[e], fa[e], sa[e], tabA, tabB, out);
    }
}

// ---------------------------------------------------------------------------
extern "C" void kernel_launch(void* const* d_in, const int* in_sizes, int n_in,
                              void* d_out, int out_size) {
    const float* rij = (const float*)d_in[0];
    const float* cr  = (const float*)d_in[1];
    const float* Z   = (const float*)d_in[2];
    const int*   fa  = (const int*)d_in[3];
    const int*   sa  = (const int*)d_in[4];
    const int*   ty  = (const int*)d_in[5];
    int E       = in_sizes[0];
    int n_atoms = out_size;
    float* out  = (float*)d_out;

    zbl_setup<<<(n_atoms + 255) / 256, 256>>>(ty, out, n_atoms);
    zbl_edge_kernel<<<1184, 256>>>(rij, fa, sa, cr, Z, out, E);
}

// round 7
// speedup vs baseline: 1.3839x; 1.0009x over previous
#include <cuda_runtime.h>
#include <cuda_bf16.h>

// ---------------------------------------------------------------------------
// ZBL screened-Coulomb pair energy with switching polynomial, scatter to atoms
//
// Inputs (metadata order):
//   0: rij             float32 [E]
//   1: covalent_radii  float32 [4]
//   2: atomic_numbers  float32 [4]
//   3: first_atom      int32   [E]
//   4: second_atom     int32   [E]
//   5: atom_type_index int32   [N]
// Output: float32 [N]
// ---------------------------------------------------------------------------

#define MAX_PACK_WORDS 16384   // up to 262144 atoms at 2 bits/atom

__device__ unsigned int g_packed[MAX_PACK_WORDS];

// ---- fused: zero output + pack atom types to 2 bits/atom ------------------
__global__ void zbl_setup(const int* __restrict__ type,
                          float* __restrict__ out, int n_atoms) {
    int i = blockIdx.x * blockDim.x + threadIdx.x;
    if (i < n_atoms) out[i] = 0.0f;
    int nw = (n_atoms + 15) >> 4;
    if (i < nw) {
        unsigned v = 0;
        int base = i << 4;
        int lim  = n_atoms - base;
        if (lim > 16) lim = 16;
        for (int k = 0; k < lim; k++)
            v |= ((unsigned)type[base + k] & 3u) << (2 * k);
        g_packed[i] = v;
    }
}

// ---- per-edge math --------------------------------------------------------
// tabA[p] = (rc, inv_a, halfFactor, A/6)   tabB[p] = (B/8, C/2)
__device__ __forceinline__ void zbl_edge(float r, int i,
                                         unsigned wi, unsigned wj,
                                         int j,
                                         const float4* __restrict__ tabA,
                                         const float2* __restrict__ tabB,
                                         float* __restrict__ out) {
    int ti = (wi >> ((i & 15) * 2)) & 3;
    int tj = (wj >> ((j & 15) * 2)) & 3;
    int p  = (ti << 2) | tj;
    float4 a4 = tabA[p];
    if (r <= a4.x) {
        float2 b2 = tabB[p];
        float x = -r * a4.y;          // -r / a
        // d_k * log2(e): exp2f maps straight to MUFU.EX2
        float s = 0.02817f * exp2f(0.29088274f * x)
                + 0.28022f * exp2f(0.58126184f * x)
                + 0.50986f * exp2f(1.35944400f * x)
                + 0.18175f * exp2f(4.61651600f * x);
        float r3  = r * r * r;
        float val = a4.z * __fdividef(s, r) + r3 * (a4.w + b2.x * r) + b2.y;
        atomicAdd(out + i, val);
    }
}

__global__ __launch_bounds__(256)
void zbl_edge_kernel(const float* __restrict__ rij,
                     const int*   __restrict__ fa,
                     const int*   __restrict__ sa,
                     const float* __restrict__ cr,
                     const float* __restrict__ Z,
                     float*       __restrict__ out,
                     int E) {
    __shared__ float4 tabA[16];
    __shared__ float2 tabB[16];

    if (threadIdx.x < 16) {
        int p = threadIdx.x;
        int ti = p >> 2, tj = p & 3;
        const float c[4] = {0.02817f, 0.28022f, 0.50986f, 0.18175f};
        const float d[4] = {0.20162f, 0.4029f, 0.94229f, 3.1998f};
        float zi = Z[ti], zj = Z[tj];
        float a     = 0.4685f / (powf(zi, 0.23f) + powf(zj, 0.23f));
        float inv_a = 1.0f / a;
        float rc    = cr[ti] + cr[tj];
        float phi = 0.f, dphi = 0.f, d2phi = 0.f;
#pragma unroll
        for (int k = 0; k < 4; k++) {
            float da = d[k] * inv_a;
            float ex = expf(-rc * da);
            phi   += c[k] * ex;
            dphi  -= c[k] * da * ex;
            d2phi += c[k] * da * da * ex;
        }
        float factor = 14.399645478425668f * zi * zj;
        float irc  = 1.0f / rc;
        float ec   = factor * irc * phi;
        float dec  = factor * irc * (-phi * irc + dphi);
        float d2ec = factor * irc * (d2phi - 2.0f * irc * dphi
                                     + 2.0f * phi * irc * irc);
        float A = (-3.0f * dec + rc * d2ec) * irc * irc;
        float B = ( 2.0f * dec - rc * d2ec) * irc * irc * irc;
        float C = -ec + rc * dec * 0.5f - rc * rc * d2ec * (1.0f / 12.0f);
        tabA[p] = make_float4(rc, inv_a, 0.5f * factor, A * (1.0f / 6.0f));
        tabB[p] = make_float2(B * 0.125f, C * 0.5f);
    }
    __syncthreads();

    int nvec = E >> 2;
    const float4* r4p = (const float4*)rij;
    const int4*   f4p = (const int4*)fa;
    const int4*   s4p = (const int4*)sa;

    for (int v = blockIdx.x * blockDim.x + threadIdx.x; v < nvec;
         v += gridDim.x * blockDim.x) {
        // Streaming (evict-first) loads: keep L1 free for g_packed residency.
        float4 r4 = __ldcs(r4p + v);
        int4   f4 = __ldcs(f4p + v);
        int4   s4 = __ldcs(s4p + v);

        // Hoisted gather batch: 8 independent L1-resident loads (MLP=8).
        unsigned wf0 = __ldg(&g_packed[f4.x >> 4]);
        unsigned wf1 = __ldg(&g_packed[f4.y >> 4]);
        unsigned wf2 = __ldg(&g_packed[f4.z >> 4]);
        unsigned wf3 = __ldg(&g_packed[f4.w >> 4]);
        unsigned ws0 = __ldg(&g_packed[s4.x >> 4]);
        unsigned ws1 = __ldg(&g_packed[s4.y >> 4]);
        unsigned ws2 = __ldg(&g_packed[s4.z >> 4]);
        unsigned ws3 = __ldg(&g_packed[s4.w >> 4]);

        zbl_edge(r4.x, f4.x, wf0, ws0, s4.x, tabA, tabB, out);
        zbl_edge(r4.y, f4.y, wf1, ws1, s4.y, tabA, tabB, out);
        zbl_edge(r4.z, f4.z, wf2, ws2, s4.z, tabA, tabB, out);
        zbl_edge(r4.w, f4.w, wf3, ws3, s4.w, tabA, tabB, out);
    }

    int tail = E & 3;
    if (blockIdx.x == 0 && (int)threadIdx.x < tail) {
        int e = (nvec << 2) + threadIdx.x;
        int i = fa[e], j = sa[e];
        zbl_edge(rij[e], i, __ldg(&g_packed[i >> 4]),
                 __ldg(&g_packed[j >> 4]), j, tabA, tabB, out);
    }
}

// ---------------------------------------------------------------------------
extern "C" void kernel_launch(void* const* d_in, const int* in_sizes, int n_in,
                              void* d_out, int out_size) {
    const float* rij = (const float*)d_in[0];
    const float* cr  = (const float*)d_in[1];
    const float* Z   = (const float*)d_in[2];
    const int*   fa  = (const int*)d_in[3];
    const int*   sa  = (const int*)d_in[4];
    const int*   ty  = (const int*)d_in[5];
    int E       = in_sizes[0];
    int n_atoms = out_size;
    float* out  = (float*)d_out;

    zbl_setup<<<(n_atoms + 255) / 256, 256>>>(ty, out, n_atoms);
    zbl_edge_kernel<<<1184, 256>>>(rij, fa, sa, cr, Z, out, E);
}